// round 3
// baseline (speedup 1.0000x reference)
#include <cuda_runtime.h>
#include <math.h>

#define Bb 64
#define Ll 128
#define Hh 128
#define Dd 16
#define NTOT (Bb*Ll*Ll)        // 1048576

// ---------------- scratch (static device globals: allowed) ----------------
__device__ float g_Wt[Hh*Dd*Hh];          // [k][d][n]   1 MB
__device__ float g_Wrt[Dd*Hh];            // [d][n]
__device__ float g_Q[(size_t)Bb*Ll*Dd*Hh];// [b][j][d][n] 64 MB
__device__ float g_c[Bb*Ll*Dd];           // [b][j][d]

// ---------------- JAX threefry2x32, PARTITIONABLE path, key = (0,1) -------
// counts1 (hi) = 0, counts2 (lo) = i;  32-bit draw = x0_final ^ x1_final.
__device__ __forceinline__ unsigned int rotl32(unsigned int v, int s) {
    return (v << s) | (v >> (32 - s));
}
__device__ __forceinline__ unsigned int threefry_bits(unsigned int i) {
    const unsigned int ks0 = 0u, ks1 = 1u, ks2 = 0x1BD11BDAu ^ 0u ^ 1u;
    unsigned int x0 = 0u + ks0;     // ctr_hi + ks0
    unsigned int x1 = i + ks1;      // ctr_lo + ks1
#define TFR(r) { x0 += x1; x1 = rotl32(x1, r) ^ x0; }
    TFR(13) TFR(15) TFR(26) TFR(6)   x0 += ks1; x1 += ks2 + 1u;
    TFR(17) TFR(29) TFR(16) TFR(24)  x0 += ks2; x1 += ks0 + 2u;
    TFR(13) TFR(15) TFR(26) TFR(6)   x0 += ks0; x1 += ks1 + 3u;
    TFR(17) TFR(29) TFR(16) TFR(24)  x0 += ks1; x1 += ks2 + 4u;
    TFR(13) TFR(15) TFR(26) TFR(6)   x0 += ks2; x1 += ks0 + 5u;
#undef TFR
    return x0 ^ x1;                  // partitionable 32-bit output
}

__device__ __forceinline__ float tanh_fast(float x) {
    // tanh(x) = 1 - 2/(exp(2x)+1); robust at +-inf of the exp.
    float e = __expf(2.0f * x);
    return 1.0f - __fdividef(2.0f, e + 1.0f);
}

// ---------------- kernel T: W[k,n,d] -> Wt[k,d,n]; Wr[n,d] -> Wrt[d,n] ----
__global__ void k_transpose(const float* __restrict__ W, const float* __restrict__ Wr) {
    int idx = blockIdx.x * blockDim.x + threadIdx.x;
    if (idx < Hh * Hh * Dd) {
        int k = idx >> 11;          // / 2048
        int rem = idx & 2047;
        int d = rem >> 7;
        int n = rem & 127;
        g_Wt[idx] = W[(k * Hh + n) * Dd + d];
    }
    if (idx < Dd * Hh) {
        int d = idx >> 7, n = idx & 127;
        g_Wrt[idx] = Wr[n * Dd + d];
    }
}

// ---------------- kernel C: c[b,j,d] = enc[b,j,:] . Wl[:,d] + Bvec[d] ----
__global__ void k_linear(const float* __restrict__ enc, const float* __restrict__ Wl,
                         const float* __restrict__ Bvec) {
    int idx = blockIdx.x * blockDim.x + threadIdx.x;    // (b*L+j)*16 + d
    if (idx >= Bb * Ll * Dd) return;
    int d = idx & 15;
    int bj = idx >> 4;
    const float* e = enc + (size_t)bj * Hh;
    float acc = Bvec[d];
#pragma unroll 8
    for (int k = 0; k < Hh; k++) acc = fmaf(e[k], Wl[k * Dd + d], acc);
    g_c[idx] = acc;
}

// ---------------- kernel 1: Q[b,j,(d,n)] = enc_b @ Wt + Wrt --------------
// per-b GEMM: A = enc_b [128 x 128], B = Wt [128 x 2048], tile 64x64, 4x4/thread
__global__ __launch_bounds__(256) void k_gemm1(const float* __restrict__ enc) {
    __shared__ float sA[Hh][68];   // [k][jj] (transposed A tile, padded)
    __shared__ float sB[32][68];   // [kk][cc]
    int b = blockIdx.z;
    int j0 = blockIdx.y * 64;
    int col0 = blockIdx.x * 64;
    int tid = threadIdx.x;
    int tx = tid & 15, ty = tid >> 4;

    // load + transpose A tile (coalesced global float4, scalar smem stores)
    const float4* e4 = (const float4*)(enc + (size_t)(b * Ll + j0) * Hh);
    for (int idx = tid; idx < 64 * 32; idx += 256) {
        int jj = idx >> 5;
        int kg = idx & 31;
        float4 v = e4[jj * 32 + kg];
        sA[kg * 4 + 0][jj] = v.x;
        sA[kg * 4 + 1][jj] = v.y;
        sA[kg * 4 + 2][jj] = v.z;
        sA[kg * 4 + 3][jj] = v.w;
    }

    float acc[4][4] = {};
    for (int kc = 0; kc < 4; kc++) {
        __syncthreads();
        int k0 = kc * 32;
        for (int idx = tid; idx < 32 * 16; idx += 256) {
            int kk = idx >> 4;
            int cg = idx & 15;
            float4 v = *(const float4*)(g_Wt + (size_t)(k0 + kk) * 2048 + col0 + cg * 4);
            *(float4*)&sB[kk][cg * 4] = v;
        }
        __syncthreads();
#pragma unroll
        for (int kk = 0; kk < 32; kk++) {
            float4 a = *(const float4*)&sA[k0 + kk][ty * 4];
            float4 bv = *(const float4*)&sB[kk][tx * 4];
            acc[0][0] = fmaf(a.x, bv.x, acc[0][0]); acc[0][1] = fmaf(a.x, bv.y, acc[0][1]);
            acc[0][2] = fmaf(a.x, bv.z, acc[0][2]); acc[0][3] = fmaf(a.x, bv.w, acc[0][3]);
            acc[1][0] = fmaf(a.y, bv.x, acc[1][0]); acc[1][1] = fmaf(a.y, bv.y, acc[1][1]);
            acc[1][2] = fmaf(a.y, bv.z, acc[1][2]); acc[1][3] = fmaf(a.y, bv.w, acc[1][3]);
            acc[2][0] = fmaf(a.z, bv.x, acc[2][0]); acc[2][1] = fmaf(a.z, bv.y, acc[2][1]);
            acc[2][2] = fmaf(a.z, bv.z, acc[2][2]); acc[2][3] = fmaf(a.z, bv.w, acc[2][3]);
            acc[3][0] = fmaf(a.w, bv.x, acc[3][0]); acc[3][1] = fmaf(a.w, bv.y, acc[3][1]);
            acc[3][2] = fmaf(a.w, bv.z, acc[3][2]); acc[3][3] = fmaf(a.w, bv.w, acc[3][3]);
        }
    }
    // epilogue: add Wrt (folds dot_r into Q), write Q
    float4 wr = *(const float4*)(g_Wrt + col0 + tx * 4);
#pragma unroll
    for (int r = 0; r < 4; r++) {
        float4 o;
        o.x = acc[r][0] + wr.x; o.y = acc[r][1] + wr.y;
        o.z = acc[r][2] + wr.z; o.w = acc[r][3] + wr.w;
        *(float4*)(g_Q + (size_t)(b * Ll + j0 + ty * 4 + r) * 2048 + col0 + tx * 4) = o;
    }
}

// ---------------- kernel 2: fused bilinear-GEMM + tanh + logits + outputs -
// block = (m-tile, j-tile, b); 64x64 output tile; loop d (16 slices of Q)
extern __shared__ float smem2[];
__global__ __launch_bounds__(256) void k_final(const float* __restrict__ enc,
                                               const float* __restrict__ U,
                                               const float* __restrict__ lb,
                                               float* __restrict__ out) {
    float* sE = smem2;             // [n][mm]: sE[n*64+mm]    32 KB
    float* sQ = smem2 + 128 * 64;  // [jj][n]: sQ[jj*128+n]   32 KB
    int b = blockIdx.z;
    int j0 = blockIdx.y * 64, m0 = blockIdx.x * 64;
    int tid = threadIdx.x, tx = tid & 15, ty = tid >> 4;

    // load enc m-tile transposed: sE[n][mm]
    const float4* e4 = (const float4*)(enc + (size_t)(b * Ll + m0) * Hh);
    for (int idx = tid; idx < 64 * 32; idx += 256) {
        int mm = idx >> 5, ng = idx & 31;
        float4 v = e4[mm * 32 + ng];
        sE[(ng * 4 + 0) * 64 + mm] = v.x;
        sE[(ng * 4 + 1) * 64 + mm] = v.y;
        sE[(ng * 4 + 2) * 64 + mm] = v.z;
        sE[(ng * 4 + 3) * 64 + mm] = v.w;
    }

    float logit[4][4] = {};
    float lbias = lb[0];

    for (int d = 0; d < Dd; d++) {
        __syncthreads();   // sE ready (d=0) / previous compute done before sQ overwrite
        const float* Qb = g_Q + (size_t)(b * Ll + j0) * 2048 + d * 128;
        for (int idx = tid; idx < 64 * 32; idx += 256) {
            int jj = idx >> 5, ng = idx & 31;
            float4 v = *(const float4*)(Qb + (size_t)jj * 2048 + ng * 4);
            *(float4*)&sQ[jj * 128 + ng * 4] = v;
        }
        __syncthreads();

        float S[4][4] = {};
#pragma unroll 4
        for (int n = 0; n < 128; n++) {
            float4 bv = *(const float4*)&sE[n * 64 + tx * 4];
            float a0 = sQ[(ty * 4 + 0) * 128 + n];
            float a1 = sQ[(ty * 4 + 1) * 128 + n];
            float a2 = sQ[(ty * 4 + 2) * 128 + n];
            float a3 = sQ[(ty * 4 + 3) * 128 + n];
            S[0][0] = fmaf(a0, bv.x, S[0][0]); S[0][1] = fmaf(a0, bv.y, S[0][1]);
            S[0][2] = fmaf(a0, bv.z, S[0][2]); S[0][3] = fmaf(a0, bv.w, S[0][3]);
            S[1][0] = fmaf(a1, bv.x, S[1][0]); S[1][1] = fmaf(a1, bv.y, S[1][1]);
            S[1][2] = fmaf(a1, bv.z, S[1][2]); S[1][3] = fmaf(a1, bv.w, S[1][3]);
            S[2][0] = fmaf(a2, bv.x, S[2][0]); S[2][1] = fmaf(a2, bv.y, S[2][1]);
            S[2][2] = fmaf(a2, bv.z, S[2][2]); S[2][3] = fmaf(a2, bv.w, S[2][3]);
            S[3][0] = fmaf(a3, bv.x, S[3][0]); S[3][1] = fmaf(a3, bv.y, S[3][1]);
            S[3][2] = fmaf(a3, bv.z, S[3][2]); S[3][3] = fmaf(a3, bv.w, S[3][3]);
        }
        float ud = U[d];
#pragma unroll
        for (int r = 0; r < 4; r++) {
            float cjd = g_c[(size_t)(b * Ll + j0 + ty * 4 + r) * 16 + d];
#pragma unroll
            for (int q = 0; q < 4; q++) {
                float t = tanh_fast(S[r][q] + cjd);
                logit[r][q] = fmaf(ud, t, logit[r][q]);
            }
        }
    }

    // epilogue: mask, sigmoid, bernoulli (threefry), entropy; write 3 outputs
    float* outS = out;
    float* outM = out + NTOT;
    float* outE = out + 2 * NTOT;
#pragma unroll
    for (int r = 0; r < 4; r++) {
        int j = j0 + ty * 4 + r;
        float vs[4], vm[4], ve[4];
#pragma unroll
        for (int q = 0; q < 4; q++) {
            int m = m0 + tx * 4 + q;
            float s = logit[r][q] + lbias;
            if (j == m) s -= 1e8f;
            float p = 1.0f / (1.0f + expf(-s));
            unsigned int i = (unsigned int)((b * Ll + j) * Ll + m);
            unsigned int bits = threefry_bits(i);
            float u = __uint_as_float((bits >> 9) | 0x3f800000u) - 1.0f;
            float samp = (u < p) ? 1.0f : 0.0f;
            float ax = fabsf(s);
            float lse = log1pf(expf(-ax));          // log1p(exp(-|s|))
            float spp = fmaxf(s, 0.0f) + lse;       // softplus(s)
            float spn = fmaxf(-s, 0.0f) + lse;      // softplus(-s)
            float ent = p * spn + (1.0f - p) * spp;
            vs[q] = samp; vm[q] = s; ve[q] = ent;
        }
        size_t o = (size_t)(b * Ll + j) * Ll + m0 + tx * 4;
        *(float4*)(outS + o) = make_float4(vs[0], vs[1], vs[2], vs[3]);
        *(float4*)(outM + o) = make_float4(vm[0], vm[1], vm[2], vm[3]);
        *(float4*)(outE + o) = make_float4(ve[0], ve[1], ve[2], ve[3]);
    }
}

// ---------------- launch ----------------
extern "C" void kernel_launch(void* const* d_in, const int* in_sizes, int n_in,
                              void* d_out, int out_size) {
    const float* enc  = (const float*)d_in[0];  // [B,L,H]
    const float* W    = (const float*)d_in[1];  // [H,H,D]
    const float* Wl   = (const float*)d_in[2];  // [H,D]
    const float* Wr   = (const float*)d_in[3];  // [H,D]
    const float* U    = (const float*)d_in[4];  // [D]
    const float* Bv   = (const float*)d_in[5];  // [D]
    const float* lbias= (const float*)d_in[6];  // [1]
    float* out = (float*)d_out;

    k_transpose<<<(Hh * Hh * Dd + 255) / 256, 256>>>(W, Wr);
    k_linear<<<(Bb * Ll * Dd + 255) / 256, 256>>>(enc, Wl, Bv);
    k_gemm1<<<dim3(32, 2, Bb), 256>>>(enc);

    int smem_bytes = (128 * 64 + 64 * 128) * (int)sizeof(float);  // 64 KB
    cudaFuncSetAttribute(k_final, cudaFuncAttributeMaxDynamicSharedMemorySize, smem_bytes);
    k_final<<<dim3(2, 2, Bb), 256, smem_bytes>>>(enc, U, lbias, out);
}